// round 7
// baseline (speedup 1.0000x reference)
#include <cuda_runtime.h>
#include <cuda_bf16.h>
#include <cstdint>

constexpr int C  = 256;
constexpr int BL = 131072;        // 512*256 == 2048*64
constexpr int MR = 384;

// fp32 stage-1 path (only touched when alpha1 != 0)
__device__ float g_X1t[(size_t)C * BL];
__device__ float g_Y1t[(size_t)C * BL];
__device__ float g_Wcat[320 * C];
// shared
__device__ float g_Fcat[(size_t)320 * BL];
__device__ float g_bcat[320];
// stage-2 tensor operands + residual, layout [j2][c], j2=(n*256+q)*64+p
__device__ __nv_bfloat16 g_Xh[(size_t)BL * C];
__device__ __nv_bfloat16 g_Xl[(size_t)BL * C];
__device__ __nv_bfloat16 g_Wh[MR * C];
__device__ __nv_bfloat16 g_Wl[MR * C];

// ---------------------------- helpers --------------------------------------
#define CP16(dst, src) asm volatile("cp.async.cg.shared.global [%0], [%1], 16;" :: "r"(dst), "l"(src))
#define CP_COMMIT() asm volatile("cp.async.commit_group;" ::: "memory")
#define CP_WAIT(N)  asm volatile("cp.async.wait_group %0;" :: "n"(N) : "memory")

__device__ __forceinline__ uint32_t smem_u32(const void* p) {
    uint32_t a;
    asm("{ .reg .u64 t; cvta.to.shared.u64 t, %1; cvt.u32.u64 %0, t; }" : "=r"(a) : "l"(p));
    return a;
}
__device__ __forceinline__ void split_bf(float f, __nv_bfloat16& h, __nv_bfloat16& l) {
    h = __float2bfloat16(f);
    l = __float2bfloat16(f - __bfloat162float(h));
}
#define MMA16816(d, a, b0, b1) \
    asm volatile("mma.sync.aligned.m16n8k16.row.col.f32.bf16.bf16.f32 " \
        "{%0,%1,%2,%3}, {%4,%5,%6,%7}, {%8,%9}, {%0,%1,%2,%3};" \
        : "+f"((d)[0]), "+f"((d)[1]), "+f"((d)[2]), "+f"((d)[3]) \
        : "r"((a)[0]), "r"((a)[1]), "r"((a)[2]), "r"((a)[3]), "r"(b0), "r"(b1))

// ---------------------------------------------------------------------------
// RARE PATH (alpha1 != 0) kernels: fp32 stage 1 (unchanged, all gated).
// ---------------------------------------------------------------------------
__global__ void __launch_bounds__(1024) k_permute_in(const float* __restrict__ x,
                                                     const float* __restrict__ a1p) {
    if (a1p[0] == 0.0f) return;
    __shared__ float t2[64][17];
    int id = blockIdx.x;
    int qh = id & 15; id >>= 4;
    int c = id & 255; id >>= 8;
    int n = id;
    int tid = threadIdx.x;
    int ph = tid >> 7, w = tid & 127;
    t2[ph * 8 + (w & 7)][w >> 3] = x[((size_t)((n * 256 + c) * 128 + qh * 8 + ph)) * 128 + w];
    __syncthreads();
    int qw = tid & 15, p = tid >> 4;
    g_X1t[(size_t)c * BL + (size_t)(n * 64 + p) * 256 + qh * 16 + qw] = t2[p][qw];
}

__global__ void k_pack_w1(const float* __restrict__ Wb, const float* __restrict__ bb,
                          const float* __restrict__ Wc, const float* __restrict__ bc,
                          const float* __restrict__ Wd, const float* __restrict__ bd,
                          const float* __restrict__ alpha) {
    if (alpha[0] == 0.0f) return;
    int i = blockIdx.x * 256 + threadIdx.x;
    if (i < 32 * 256)        g_Wcat[i] = Wb[i];
    else if (i < 64 * 256)   g_Wcat[i] = Wc[i - 32 * 256];
    else if (i < 320 * 256)  g_Wcat[i] = Wd[i - 64 * 256];
    if (i < 32)              g_bcat[i] = bb[i];
    else if (i < 64)         g_bcat[i] = bc[i - 32];
    else if (i < 320)        g_bcat[i] = bd[i - 64];
}

__global__ void __launch_bounds__(256) k_gemm1(const float* __restrict__ alpha) {
    if (alpha[0] == 0.0f) return;
    __shared__ float Ws[16][64];
    __shared__ float Xs[16][64];
    int tid = threadIdx.x;
    int row0 = blockIdx.y * 64, col0 = blockIdx.x * 64;
    int tx = tid & 15, ty = tid >> 4;
    int wr = tid >> 2, wk = (tid & 3) * 4;
    int xk = tid >> 4, xj = (tid & 15) * 4;
    float acc[4][4] = {};
    for (int k0 = 0; k0 < 256; k0 += 16) {
        float4 w4 = *(const float4*)(&g_Wcat[(row0 + wr) * 256 + k0 + wk]);
        Ws[wk][wr] = w4.x; Ws[wk + 1][wr] = w4.y; Ws[wk + 2][wr] = w4.z; Ws[wk + 3][wr] = w4.w;
        *(float4*)(&Xs[xk][xj]) = *(const float4*)(&g_X1t[(size_t)(k0 + xk) * BL + col0 + xj]);
        __syncthreads();
#pragma unroll
        for (int kk = 0; kk < 16; kk++) {
            float4 a = *(const float4*)(&Ws[kk][ty * 4]);
            float4 b = *(const float4*)(&Xs[kk][tx * 4]);
            acc[0][0] += a.x * b.x; acc[0][1] += a.x * b.y; acc[0][2] += a.x * b.z; acc[0][3] += a.x * b.w;
            acc[1][0] += a.y * b.x; acc[1][1] += a.y * b.y; acc[1][2] += a.y * b.z; acc[1][3] += a.y * b.w;
            acc[2][0] += a.z * b.x; acc[2][1] += a.z * b.y; acc[2][2] += a.z * b.z; acc[2][3] += a.z * b.w;
            acc[3][0] += a.w * b.x; acc[3][1] += a.w * b.y; acc[3][2] += a.w * b.z; acc[3][3] += a.w * b.w;
        }
        __syncthreads();
    }
#pragma unroll
    for (int i = 0; i < 4; i++) {
        int row = row0 + ty * 4 + i;
        float bi = g_bcat[row];
        float4 v = make_float4(acc[i][0] + bi, acc[i][1] + bi, acc[i][2] + bi, acc[i][3] + bi);
        *(float4*)(&g_Fcat[(size_t)row * BL + col0 + tx * 4]) = v;
    }
}

__global__ void __launch_bounds__(256) k_attn1(const float* __restrict__ ap) {
    float alpha = ap[0];
    if (alpha == 0.0f) return;
    __shared__ float fb_s[32 * 32];
    __shared__ float P[32 * 257];
    int b = blockIdx.x >> 3, l0 = (blockIdx.x & 7) * 32, t = threadIdx.x;
    size_t colbase = (size_t)b * 256;
    const float* __restrict__ FB = g_Fcat;
    const float* __restrict__ FC = g_Fcat + (size_t)32 * BL;
    const float* __restrict__ FD = g_Fcat + (size_t)64 * BL;
    for (int idx = t; idx < 32 * 32; idx += 256) {
        int o = idx >> 5, lt = idx & 31;
        fb_s[o * 32 + lt] = FB[(size_t)o * BL + colbase + l0 + lt];
    }
    __syncthreads();
    for (int idx = t; idx < 32 * 256; idx += 256) {
        int lt = idx >> 8, m = idx & 255;
        float acc = 0.0f;
#pragma unroll
        for (int o = 0; o < 32; o++) acc += fb_s[o * 32 + lt] * FC[(size_t)o * BL + colbase + m];
        P[lt * 257 + m] = acc;
    }
    __syncthreads();
    int warp = t >> 5, lane = t & 31;
    for (int lt = warp; lt < 32; lt += 8) {
        float mx = -3.4e38f;
        for (int m = lane; m < 256; m += 32) mx = fmaxf(mx, P[lt * 257 + m]);
#pragma unroll
        for (int o = 16; o > 0; o >>= 1) mx = fmaxf(mx, __shfl_xor_sync(0xffffffffu, mx, o));
        float s = 0.0f;
        for (int m = lane; m < 256; m += 32) {
            float e = __expf(P[lt * 257 + m] - mx);
            P[lt * 257 + m] = e; s += e;
        }
#pragma unroll
        for (int o = 16; o > 0; o >>= 1) s += __shfl_xor_sync(0xffffffffu, s, o);
        float inv = 1.0f / s;
        for (int m = lane; m < 256; m += 32) P[lt * 257 + m] *= inv;
    }
    __syncthreads();
    for (int c0 = 0; c0 < 256; c0 += 32) {
        int lt = t & 31, ci0 = (t >> 5) * 4;
        float a0 = 0, a1 = 0, a2 = 0, a3 = 0;
        for (int m = 0; m < 256; m++) {
            float pv = P[lt * 257 + m];
            a0 += FD[(size_t)(c0 + ci0 + 0) * BL + colbase + m] * pv;
            a1 += FD[(size_t)(c0 + ci0 + 1) * BL + colbase + m] * pv;
            a2 += FD[(size_t)(c0 + ci0 + 2) * BL + colbase + m] * pv;
            a3 += FD[(size_t)(c0 + ci0 + 3) * BL + colbase + m] * pv;
        }
        int l = l0 + lt;
        float r[4] = {a0, a1, a2, a3};
#pragma unroll
        for (int k = 0; k < 4; k++) {
            size_t o = (size_t)(c0 + ci0 + k) * BL + colbase + l;
            g_Y1t[o] = alpha * r[k] + g_X1t[o];
        }
    }
}

// ---------------------------------------------------------------------------
// Build stage-2 operand/residual: [j2][c] bf16 hi/lo.
// mode 0: gated a1==0, reads x.   mode 1: gated a1!=0, reads Y1t.
// ---------------------------------------------------------------------------
__global__ void __launch_bounds__(256) k_make_X2(const float* __restrict__ x,
                                                 const float* __restrict__ a1p, int mode) {
    float a1 = a1p[0];
    if (mode == 0 && a1 != 0.0f) return;
    if (mode == 1 && a1 == 0.0f) return;
    bool from_x = (mode == 0);
    __shared__ float sm[64 * 65];
    int id = blockIdx.x;
    int qw = id & 15, qh = (id >> 4) & 15, n = id >> 8;
    int q = qh * 16 + qw;
    int t = threadIdx.x;
    for (int c0 = 0; c0 < 256; c0 += 64) {
        if (from_x) {
#pragma unroll
            for (int it = 0; it < 2; it++) {
                int task = t + it * 256;
                int cl = task >> 3, ph = task & 7;
                const float* src = &x[(((size_t)(n * 256 + c0 + cl) * 128) + qh * 8 + ph) * 128 + qw * 8];
                float4 v0 = *(const float4*)src;
                float4 v1 = *(const float4*)(src + 4);
                int pb = ph * 8;
                sm[(pb + 0) * 65 + cl] = v0.x; sm[(pb + 1) * 65 + cl] = v0.y;
                sm[(pb + 2) * 65 + cl] = v0.z; sm[(pb + 3) * 65 + cl] = v0.w;
                sm[(pb + 4) * 65 + cl] = v1.x; sm[(pb + 5) * 65 + cl] = v1.y;
                sm[(pb + 6) * 65 + cl] = v1.z; sm[(pb + 7) * 65 + cl] = v1.w;
            }
        } else {
            for (int idx = t; idx < 64 * 64; idx += 256) {
                int cl = idx & 63, p = idx >> 6;
                sm[p * 65 + cl] = g_Y1t[(size_t)(c0 + cl) * BL + (size_t)(n * 64 + p) * 256 + q];
            }
        }
        __syncthreads();
        int p = t >> 2, seg = t & 3;
        __nv_bfloat16 hv[16], lv[16];
#pragma unroll
        for (int i = 0; i < 16; i++) split_bf(sm[p * 65 + seg * 16 + i], hv[i], lv[i]);
        size_t off = ((size_t)(n * 256 + q) * 64 + p) * 256 + c0 + seg * 16;
        *(uint4*)&g_Xh[off]     = *(uint4*)&hv[0];
        *(uint4*)&g_Xh[off + 8] = *(uint4*)&hv[8];
        *(uint4*)&g_Xl[off]     = *(uint4*)&lv[0];
        *(uint4*)&g_Xl[off + 8] = *(uint4*)&lv[8];
        __syncthreads();
    }
}

__global__ void k_pack_w2(const float* __restrict__ Wb, const float* __restrict__ bb,
                          const float* __restrict__ Wc, const float* __restrict__ bc,
                          const float* __restrict__ Wd, const float* __restrict__ bd,
                          const float* __restrict__ alpha) {
    if (alpha[0] == 0.0f) return;
    int i = blockIdx.x * 256 + threadIdx.x;
    int r = i >> 8, c = i & 255;
    float w = 0.0f;
    if (r < 32)       w = Wb[r * 256 + c];
    else if (r < 64)  w = Wc[(r - 32) * 256 + c];
    else if (r < 320) w = Wd[(r - 64) * 256 + c];
    __nv_bfloat16 h, l; split_bf(w, h, l);
    g_Wh[i] = h; g_Wl[i] = l;
    if (i < 320) g_bcat[i] = (i < 32) ? bb[i] : (i < 64) ? bc[i - 32] : bd[i - 64];
}

// ---------------------------------------------------------------------------
// Split bf16 GEMM via mma.sync.m16n8k16.
// Tile M=64 x N=128, K-chunks 64, double-buffered -> 55 KB/stage, 2 CTAs/SM.
// 8 warps = 2M x 4N. 3 separated product passes (AhBh | AhBl | AlBh) so the
// accumulator-reuse distance is 8 MMAs instead of 1.
// ---------------------------------------------------------------------------
constexpr int PAD    = 72;                    // bf16 per smem row
constexpr int OFF_AL = 64 * PAD;
constexpr int OFF_BH = 128 * PAD;
constexpr int OFF_BL = 256 * PAD;
constexpr int STAGE  = 384 * PAD;             // 27648 bf16 = 55296 B

__global__ void __launch_bounds__(256) k_gemm_mma(const float* __restrict__ a1p,
                                                  const float* __restrict__ a2p, int phase) {
    float a1 = a1p[0];
    if (phase == 0 && a1 != 0.0f) return;
    if (phase == 1 && a1 == 0.0f) return;
    if (a2p[0] == 0.0f) return;

    extern __shared__ __nv_bfloat16 smb[];
    int t = threadIdx.x, w = t >> 5, lane = t & 31;
    int g = lane >> 2, tg = lane & 3;
    int mt = blockIdx.x;                 // 0..4, fast dim for B L2 reuse
    size_t j0 = (size_t)blockIdx.y * 128;

    uint32_t sbase = smem_u32(smb);
    const __nv_bfloat16* Asrc_h = g_Wh + (size_t)mt * 64 * 256;
    const __nv_bfloat16* Asrc_l = g_Wl + (size_t)mt * 64 * 256;
    const __nv_bfloat16* Bsrc_h = g_Xh + j0 * 256;
    const __nv_bfloat16* Bsrc_l = g_Xl + j0 * 256;

    auto load_chunk = [&](int kc, int s) {
        int k0 = kc * 64;
        uint32_t st = sbase + (uint32_t)s * (STAGE * 2);
        {   // A: 128 rows (hi 0-63, lo 64-127), thread t -> row t>>1, half t&1
            int r = t >> 1, half = (t & 1) * 4;
            const __nv_bfloat16* src =
                ((r < 64) ? (Asrc_h + (size_t)r * 256) : (Asrc_l + (size_t)(r - 64) * 256))
                + k0 + half * 8;
            uint32_t dst = st + (uint32_t)r * (PAD * 2) + half * 16;
#pragma unroll
            for (int s8 = 0; s8 < 4; s8++) CP16(dst + s8 * 16, src + s8 * 8);
        }
        {   // B: 256 rows (hi 0-127, lo 128-255), thread t -> full row t
            const __nv_bfloat16* src =
                ((t < 128) ? (Bsrc_h + (size_t)t * 256) : (Bsrc_l + (size_t)(t - 128) * 256)) + k0;
            uint32_t dst = st + (uint32_t)(128 + t) * (PAD * 2);
#pragma unroll
            for (int s8 = 0; s8 < 8; s8++) CP16(dst + s8 * 16, src + s8 * 8);
        }
        CP_COMMIT();
    };

    float d[2][4][4] = {};
    int wm = (w >> 2) * 32;          // warp M offset (0 or 32)
    int wn = (w & 3) * 32;           // warp N offset (0,32,64,96)

    load_chunk(0, 0);
    load_chunk(1, 1);

#pragma unroll 1
    for (int c = 0; c < 4; c++) {
        if (c < 3) { CP_WAIT(1); } else { CP_WAIT(0); }
        __syncthreads();
        const __nv_bfloat16* stp = smb + (c & 1) * STAGE;
        const __nv_bfloat16* Ah = stp;
        const __nv_bfloat16* Al = stp + OFF_AL;
        const __nv_bfloat16* Bh = stp + OFF_BH;
        const __nv_bfloat16* Blo = stp + OFF_BL;
#pragma unroll
        for (int ks = 0; ks < 4; ks++) {
            int k0 = ks * 16;
            uint32_t ah[2][4], al[2][4], bh[4][2], bl[4][2];
#pragma unroll
            for (int mf = 0; mf < 2; mf++) {
                int row = wm + mf * 16 + g;
                ah[mf][0] = *(const uint32_t*)&Ah[row * PAD + k0 + 2 * tg];
                ah[mf][1] = *(const uint32_t*)&Ah[(row + 8) * PAD + k0 + 2 * tg];
                ah[mf][2] = *(const uint32_t*)&Ah[row * PAD + k0 + 8 + 2 * tg];
                ah[mf][3] = *(const uint32_t*)&Ah[(row + 8) * PAD + k0 + 8 + 2 * tg];
                al[mf][0] = *(const uint32_t*)&Al[row * PAD + k0 + 2 * tg];
                al[mf][1] = *(const uint32_t*)&Al[(row + 8) * PAD + k0 + 2 * tg];
                al[mf][2] = *(const uint32_t*)&Al[row * PAD + k0 + 8 + 2 * tg];
                al[mf][3] = *(const uint32_t*)&Al[(row + 8) * PAD + k0 + 8 + 2 * tg];
            }
#pragma unroll
            for (int nf = 0; nf < 4; nf++) {
                int col = wn + nf * 8 + g;
                bh[nf][0] = *(const uint32_t*)&Bh[col * PAD + k0 + 2 * tg];
                bh[nf][1] = *(const uint32_t*)&Bh[col * PAD + k0 + 8 + 2 * tg];
                bl[nf][0] = *(const uint32_t*)&Blo[col * PAD + k0 + 2 * tg];
                bl[nf][1] = *(const uint32_t*)&Blo[col * PAD + k0 + 8 + 2 * tg];
            }
            // pass 1: Ah * Bh
#pragma unroll
            for (int nf = 0; nf < 4; nf++)
#pragma unroll
                for (int mf = 0; mf < 2; mf++) MMA16816(d[mf][nf], ah[mf], bh[nf][0], bh[nf][1]);
            // pass 2: Ah * Bl
#pragma unroll
            for (int nf = 0; nf < 4; nf++)
#pragma unroll
                for (int mf = 0; mf < 2; mf++) MMA16816(d[mf][nf], ah[mf], bl[nf][0], bl[nf][1]);
            // pass 3: Al * Bh
#pragma unroll
            for (int nf = 0; nf < 4; nf++)
#pragma unroll
                for (int mf = 0; mf < 2; mf++) MMA16816(d[mf][nf], al[mf], bh[nf][0], bh[nf][1]);
        }
        __syncthreads();
        if (c + 2 < 4) load_chunk(c + 2, c & 1);
    }

#pragma unroll
    for (int mf = 0; mf < 2; mf++) {
        int row = mt * 64 + wm + mf * 16 + g;
        float b0 = g_bcat[row], b1 = g_bcat[row + 8];
#pragma unroll
        for (int nf = 0; nf < 4; nf++) {
            size_t col = j0 + wn + nf * 8 + 2 * tg;
            *(float2*)&g_Fcat[(size_t)row * BL + col] =
                make_float2(d[mf][nf][0] + b0, d[mf][nf][1] + b0);
            *(float2*)&g_Fcat[(size_t)(row + 8) * BL + col] =
                make_float2(d[mf][nf][2] + b1, d[mf][nf][3] + b1);
        }
    }
}

// ---------------------------------------------------------------------------
// Stage-2 attention (L=64) + residual + final NCHW store.
// ---------------------------------------------------------------------------
__global__ void __launch_bounds__(256) k_attn2(const float* __restrict__ a1p,
                                               const float* __restrict__ a2p,
                                               float* __restrict__ out, int phase) {
    float a1 = a1p[0];
    if (phase == 0 && a1 != 0.0f) return;
    if (phase == 1 && a1 == 0.0f) return;
    __shared__ float fb_s[32 * 64];
    __shared__ float fc_s[32 * 65];
    __shared__ float P[64 * 65];
    __shared__ float fd_s[64 * 36];
    int b = blockIdx.x, t = threadIdx.x;
    float alpha = a2p[0];
    size_t colbase = (size_t)b * 64;
    int n = b >> 8, q = b & 255, qh = q >> 4, qw = q & 15;

    if (alpha == 0.0f) {
        for (int idx = t; idx < 256 * 64; idx += 256) {
            int c = idx & 255, l = idx >> 8;
            size_t src = (colbase + l) * 256 + c;
            float v = __bfloat162float(g_Xh[src]) + __bfloat162float(g_Xl[src]);
            int ph = l >> 3, pw = l & 7;
            out[((size_t)(n * 256 + c) * 128 + qh * 8 + ph) * 128 + qw * 8 + pw] = v;
        }
        return;
    }

    const float* __restrict__ FB = g_Fcat;
    const float* __restrict__ FC = g_Fcat + (size_t)32 * BL;
    const float* __restrict__ FD = g_Fcat + (size_t)64 * BL;

    for (int idx = t; idx < 32 * 64; idx += 256) {
        int o = idx >> 6, m = idx & 63;
        fb_s[o * 64 + m] = FB[(size_t)o * BL + colbase + m];
        fc_s[o * 65 + m] = FC[(size_t)o * BL + colbase + m];
    }
    __syncthreads();

    for (int idx = t; idx < 64 * 64; idx += 256) {
        int lt = idx >> 6, m = idx & 63;
        float acc = 0.0f;
#pragma unroll
        for (int o = 0; o < 32; o++) acc += fb_s[o * 64 + lt] * fc_s[o * 65 + m];
        P[lt * 65 + m] = acc;
    }
    __syncthreads();

    int warp = t >> 5, lane = t & 31;
    for (int lt = warp; lt < 64; lt += 8) {
        float v0 = P[lt * 65 + lane], v1 = P[lt * 65 + 32 + lane];
        float mx = fmaxf(v0, v1);
#pragma unroll
        for (int o = 16; o > 0; o >>= 1) mx = fmaxf(mx, __shfl_xor_sync(0xffffffffu, mx, o));
        float e0 = __expf(v0 - mx), e1 = __expf(v1 - mx);
        float s = e0 + e1;
#pragma unroll
        for (int o = 16; o > 0; o >>= 1) s += __shfl_xor_sync(0xffffffffu, s, o);
        float inv = 1.0f / s;
        P[lt * 65 + lane] = e0 * inv;
        P[lt * 65 + 32 + lane] = e1 * inv;
    }
    __syncthreads();

    for (int c0 = 0; c0 < 256; c0 += 32) {
        for (int idx = t; idx < 32 * 64; idx += 256) {
            int m = idx & 63, ci = idx >> 6;
            fd_s[m * 36 + ci] = FD[(size_t)(c0 + ci) * BL + colbase + m];
        }
        __syncthreads();
        for (int idx = t; idx < 512; idx += 256) {
            int lt = idx & 63, ci0 = (idx >> 6) * 4;
            unsigned long long acc0 = 0ull, acc1 = 0ull;
#pragma unroll 4
            for (int m = 0; m < 64; m++) {
                float pv = P[lt * 65 + m];
                unsigned long long pp;
                asm("mov.b64 %0, {%1,%1};" : "=l"(pp) : "r"(__float_as_uint(pv)));
                ulonglong2 f2 = *(const ulonglong2*)&fd_s[m * 36 + ci0];
                asm("fma.rn.f32x2 %0, %1, %2, %3;" : "=l"(acc0) : "l"(f2.x), "l"(pp), "l"(acc0));
                asm("fma.rn.f32x2 %0, %1, %2, %3;" : "=l"(acc1) : "l"(f2.y), "l"(pp), "l"(acc1));
            }
            uint32_t u0, u1, u2, u3;
            asm("mov.b64 {%0,%1}, %2;" : "=r"(u0), "=r"(u1) : "l"(acc0));
            asm("mov.b64 {%0,%1}, %2;" : "=r"(u2), "=r"(u3) : "l"(acc1));
            float a[4] = {__uint_as_float(u0), __uint_as_float(u1),
                          __uint_as_float(u2), __uint_as_float(u3)};
            int ph = lt >> 3, pw = lt & 7;
            const __nv_bfloat16* xh = &g_Xh[(colbase + lt) * 256 + c0 + ci0];
            const __nv_bfloat16* xl = &g_Xl[(colbase + lt) * 256 + c0 + ci0];
            size_t o0 = ((size_t)(n * 256 + c0 + ci0) * 128 + qh * 8 + ph) * 128 + qw * 8 + pw;
#pragma unroll
            for (int k = 0; k < 4; k++)
                out[o0 + (size_t)k * 16384] =
                    alpha * a[k] + __bfloat162float(xh[k]) + __bfloat162float(xl[k]);
        }
        __syncthreads();
    }
}

// ---------------------------------------------------------------------------
extern "C" void kernel_launch(void* const* d_in, const int* in_sizes, int n_in,
                              void* d_out, int out_size) {
    (void)in_sizes; (void)n_in; (void)out_size;
    const float* x   = (const float*)d_in[0];
    const float* Wb1 = (const float*)d_in[1];
    const float* bb1 = (const float*)d_in[2];
    const float* Wc1 = (const float*)d_in[3];
    const float* bc1 = (const float*)d_in[4];
    const float* Wd1 = (const float*)d_in[5];
    const float* bd1 = (const float*)d_in[6];
    const float* a1  = (const float*)d_in[7];
    const float* Wb2 = (const float*)d_in[8];
    const float* bb2 = (const float*)d_in[9];
    const float* Wc2 = (const float*)d_in[10];
    const float* bc2 = (const float*)d_in[11];
    const float* Wd2 = (const float*)d_in[12];
    const float* bd2 = (const float*)d_in[13];
    const float* a2  = (const float*)d_in[14];
    float* out = (float*)d_out;

    constexpr int GSM = 2 * STAGE * 2;   // 110592 bytes
    cudaFuncSetAttribute(k_gemm_mma, cudaFuncAttributeMaxDynamicSharedMemorySize, GSM);

    // ---- fast path (alpha1 == 0; all kernels gated on-device) ----
    k_make_X2<<<2048, 256>>>(x, a1, 0);                            // launch 0
    k_pack_w2<<<MR, 256>>>(Wb2, bb2, Wc2, bc2, Wd2, bd2, a2);      // launch 1
    k_pack_w1<<<320, 256>>>(Wb1, bb1, Wc1, bc1, Wd1, bd1, a1);     // launch 2 (rare prep)
    k_gemm_mma<<<dim3(5, BL / 128), 256, GSM>>>(a1, a2, 0);        // launch 3  <- profiled
    k_attn2<<<2048, 256>>>(a1, a2, out, 0);                        // launch 4

    // ---- rare path (alpha1 != 0; all no-ops otherwise) ----
    k_permute_in<<<8 * 256 * 16, 1024>>>(x, a1);
    k_gemm1<<<dim3(BL / 64, 5), 256>>>(a1);
    k_attn1<<<512 * 8, 256>>>(a1);
    k_make_X2<<<2048, 256>>>(x, a1, 1);
    k_gemm_mma<<<dim3(5, BL / 128), 256, GSM>>>(a1, a2, 1);
    k_attn2<<<2048, 256>>>(a1, a2, out, 1);
}

// round 9
// speedup vs baseline: 1.9290x; 1.9290x over previous
#include <cuda_runtime.h>
#include <cuda_bf16.h>
#include <cuda_fp16.h>
#include <cstdint>

constexpr int C  = 256;
constexpr int BL = 131072;        // 512*256 == 2048*64
constexpr int MR = 384;

// fp32 stage-1 path (only touched when alpha1 != 0)
__device__ float g_X1t[(size_t)C * BL];
__device__ float g_Y1t[(size_t)C * BL];
__device__ float g_Wcat[320 * C];
// shared
__device__ float g_Fcat[(size_t)320 * BL];
__device__ float g_bcat[320];
// stage-2 fp16 operands, layout [j2][c], j2=(n*256+q)*64+p
__device__ __half g_Xh[(size_t)BL * C];
__device__ __half g_Wh[MR * C];

// ---------------------------- helpers --------------------------------------
#define CP16(dst, src) asm volatile("cp.async.cg.shared.global [%0], [%1], 16;" :: "r"(dst), "l"(src))
#define CP_COMMIT() asm volatile("cp.async.commit_group;" ::: "memory")
#define CP_WAIT(N)  asm volatile("cp.async.wait_group %0;" :: "n"(N) : "memory")

__device__ __forceinline__ uint32_t smem_u32(const void* p) {
    uint32_t a;
    asm("{ .reg .u64 t; cvta.to.shared.u64 t, %1; cvt.u32.u64 %0, t; }" : "=r"(a) : "l"(p));
    return a;
}
#define LDSM_X4(r0, r1, r2, r3, addr) \
    asm volatile("ldmatrix.sync.aligned.m8n8.x4.shared.b16 {%0,%1,%2,%3}, [%4];" \
        : "=r"(r0), "=r"(r1), "=r"(r2), "=r"(r3) : "r"(addr))
#define MMA16816H(d, a, b0, b1) \
    asm volatile("mma.sync.aligned.m16n8k16.row.col.f32.f16.f16.f32 " \
        "{%0,%1,%2,%3}, {%4,%5,%6,%7}, {%8,%9}, {%0,%1,%2,%3};" \
        : "+f"((d)[0]), "+f"((d)[1]), "+f"((d)[2]), "+f"((d)[3]) \
        : "r"((a)[0]), "r"((a)[1]), "r"((a)[2]), "r"((a)[3]), "r"(b0), "r"(b1))

// ---------------------------------------------------------------------------
// RARE PATH (alpha1 != 0): exact fp32 stage 1 (gated on-device).
// ---------------------------------------------------------------------------
__global__ void __launch_bounds__(1024) k_permute_in(const float* __restrict__ x,
                                                     const float* __restrict__ a1p) {
    if (a1p[0] == 0.0f) return;
    __shared__ float t2[64][17];
    int id = blockIdx.x;
    int qh = id & 15; id >>= 4;
    int c = id & 255; id >>= 8;
    int n = id;
    int tid = threadIdx.x;
    int ph = tid >> 7, w = tid & 127;
    t2[ph * 8 + (w & 7)][w >> 3] = x[((size_t)((n * 256 + c) * 128 + qh * 8 + ph)) * 128 + w];
    __syncthreads();
    int qw = tid & 15, p = tid >> 4;
    g_X1t[(size_t)c * BL + (size_t)(n * 64 + p) * 256 + qh * 16 + qw] = t2[p][qw];
}

__global__ void k_pack_w1(const float* __restrict__ Wb, const float* __restrict__ bb,
                          const float* __restrict__ Wc, const float* __restrict__ bc,
                          const float* __restrict__ Wd, const float* __restrict__ bd,
                          const float* __restrict__ alpha) {
    if (alpha[0] == 0.0f) return;
    int i = blockIdx.x * 256 + threadIdx.x;
    if (i < 32 * 256)        g_Wcat[i] = Wb[i];
    else if (i < 64 * 256)   g_Wcat[i] = Wc[i - 32 * 256];
    else if (i < 320 * 256)  g_Wcat[i] = Wd[i - 64 * 256];
    if (i < 32)              g_bcat[i] = bb[i];
    else if (i < 64)         g_bcat[i] = bc[i - 32];
    else if (i < 320)        g_bcat[i] = bd[i - 64];
}

__global__ void __launch_bounds__(256) k_gemm1(const float* __restrict__ alpha) {
    if (alpha[0] == 0.0f) return;
    __shared__ float Ws[16][64];
    __shared__ float Xs[16][64];
    int tid = threadIdx.x;
    int row0 = blockIdx.y * 64, col0 = blockIdx.x * 64;
    int tx = tid & 15, ty = tid >> 4;
    int wr = tid >> 2, wk = (tid & 3) * 4;
    int xk = tid >> 4, xj = (tid & 15) * 4;
    float acc[4][4] = {};
    for (int k0 = 0; k0 < 256; k0 += 16) {
        float4 w4 = *(const float4*)(&g_Wcat[(row0 + wr) * 256 + k0 + wk]);
        Ws[wk][wr] = w4.x; Ws[wk + 1][wr] = w4.y; Ws[wk + 2][wr] = w4.z; Ws[wk + 3][wr] = w4.w;
        *(float4*)(&Xs[xk][xj]) = *(const float4*)(&g_X1t[(size_t)(k0 + xk) * BL + col0 + xj]);
        __syncthreads();
#pragma unroll
        for (int kk = 0; kk < 16; kk++) {
            float4 a = *(const float4*)(&Ws[kk][ty * 4]);
            float4 b = *(const float4*)(&Xs[kk][tx * 4]);
            acc[0][0] += a.x * b.x; acc[0][1] += a.x * b.y; acc[0][2] += a.x * b.z; acc[0][3] += a.x * b.w;
            acc[1][0] += a.y * b.x; acc[1][1] += a.y * b.y; acc[1][2] += a.y * b.z; acc[1][3] += a.y * b.w;
            acc[2][0] += a.z * b.x; acc[2][1] += a.z * b.y; acc[2][2] += a.z * b.z; acc[2][3] += a.z * b.w;
            acc[3][0] += a.w * b.x; acc[3][1] += a.w * b.y; acc[3][2] += a.w * b.z; acc[3][3] += a.w * b.w;
        }
        __syncthreads();
    }
#pragma unroll
    for (int i = 0; i < 4; i++) {
        int row = row0 + ty * 4 + i;
        float bi = g_bcat[row];
        float4 v = make_float4(acc[i][0] + bi, acc[i][1] + bi, acc[i][2] + bi, acc[i][3] + bi);
        *(float4*)(&g_Fcat[(size_t)row * BL + col0 + tx * 4]) = v;
    }
}

__global__ void __launch_bounds__(256) k_attn1(const float* __restrict__ ap) {
    float alpha = ap[0];
    if (alpha == 0.0f) return;
    __shared__ float fb_s[32 * 32];
    __shared__ float P[32 * 257];
    int b = blockIdx.x >> 3, l0 = (blockIdx.x & 7) * 32, t = threadIdx.x;
    size_t colbase = (size_t)b * 256;
    const float* __restrict__ FB = g_Fcat;
    const float* __restrict__ FC = g_Fcat + (size_t)32 * BL;
    const float* __restrict__ FD = g_Fcat + (size_t)64 * BL;
    for (int idx = t; idx < 32 * 32; idx += 256) {
        int o = idx >> 5, lt = idx & 31;
        fb_s[o * 32 + lt] = FB[(size_t)o * BL + colbase + l0 + lt];
    }
    __syncthreads();
    for (int idx = t; idx < 32 * 256; idx += 256) {
        int lt = idx >> 8, m = idx & 255;
        float acc = 0.0f;
#pragma unroll
        for (int o = 0; o < 32; o++) acc += fb_s[o * 32 + lt] * FC[(size_t)o * BL + colbase + m];
        P[lt * 257 + m] = acc;
    }
    __syncthreads();
    int warp = t >> 5, lane = t & 31;
    for (int lt = warp; lt < 32; lt += 8) {
        float mx = -3.4e38f;
        for (int m = lane; m < 256; m += 32) mx = fmaxf(mx, P[lt * 257 + m]);
#pragma unroll
        for (int o = 16; o > 0; o >>= 1) mx = fmaxf(mx, __shfl_xor_sync(0xffffffffu, mx, o));
        float s = 0.0f;
        for (int m = lane; m < 256; m += 32) {
            float e = __expf(P[lt * 257 + m] - mx);
            P[lt * 257 + m] = e; s += e;
        }
#pragma unroll
        for (int o = 16; o > 0; o >>= 1) s += __shfl_xor_sync(0xffffffffu, s, o);
        float inv = 1.0f / s;
        for (int m = lane; m < 256; m += 32) P[lt * 257 + m] *= inv;
    }
    __syncthreads();
    for (int c0 = 0; c0 < 256; c0 += 32) {
        int lt = t & 31, ci0 = (t >> 5) * 4;
        float a0 = 0, a1 = 0, a2 = 0, a3 = 0;
        for (int m = 0; m < 256; m++) {
            float pv = P[lt * 257 + m];
            a0 += FD[(size_t)(c0 + ci0 + 0) * BL + colbase + m] * pv;
            a1 += FD[(size_t)(c0 + ci0 + 1) * BL + colbase + m] * pv;
            a2 += FD[(size_t)(c0 + ci0 + 2) * BL + colbase + m] * pv;
            a3 += FD[(size_t)(c0 + ci0 + 3) * BL + colbase + m] * pv;
        }
        int l = l0 + lt;
        float r[4] = {a0, a1, a2, a3};
#pragma unroll
        for (int k = 0; k < 4; k++) {
            size_t o = (size_t)(c0 + ci0 + k) * BL + colbase + l;
            g_Y1t[o] = alpha * r[k] + g_X1t[o];
        }
    }
}

// ---------------------------------------------------------------------------
// Build stage-2 fp16 operand: Xh[j2][c].
// mode 0 (a1==0): read NCHW x.   mode 1 (a1!=0): read Y1t.
// ---------------------------------------------------------------------------
__global__ void __launch_bounds__(256) k_make_X2(const float* __restrict__ x,
                                                 const float* __restrict__ a1p, int mode) {
    float a1 = a1p[0];
    if (mode == 0 && a1 != 0.0f) return;
    if (mode == 1 && a1 == 0.0f) return;
    bool from_x = (mode == 0);
    __shared__ float sm[64 * 65];
    int id = blockIdx.x;
    int qw = id & 15, qh = (id >> 4) & 15, n = id >> 8;
    int q = qh * 16 + qw;
    int t = threadIdx.x;
    for (int c0 = 0; c0 < 256; c0 += 64) {
        if (from_x) {
#pragma unroll
            for (int it = 0; it < 2; it++) {
                int task = t + it * 256;
                int cl = task >> 3, ph = task & 7;
                const float* src = &x[(((size_t)(n * 256 + c0 + cl) * 128) + qh * 8 + ph) * 128 + qw * 8];
                float4 v0 = *(const float4*)src;
                float4 v1 = *(const float4*)(src + 4);
                int pb = ph * 8;
                sm[(pb + 0) * 65 + cl] = v0.x; sm[(pb + 1) * 65 + cl] = v0.y;
                sm[(pb + 2) * 65 + cl] = v0.z; sm[(pb + 3) * 65 + cl] = v0.w;
                sm[(pb + 4) * 65 + cl] = v1.x; sm[(pb + 5) * 65 + cl] = v1.y;
                sm[(pb + 6) * 65 + cl] = v1.z; sm[(pb + 7) * 65 + cl] = v1.w;
            }
        } else {
            for (int idx = t; idx < 64 * 64; idx += 256) {
                int cl = idx & 63, p = idx >> 6;
                sm[p * 65 + cl] = g_Y1t[(size_t)(c0 + cl) * BL + (size_t)(n * 64 + p) * 256 + q];
            }
        }
        __syncthreads();
        int p = t >> 2, seg = t & 3;
        __half hv[16];
#pragma unroll
        for (int i = 0; i < 16; i++) hv[i] = __float2half(sm[p * 65 + seg * 16 + i]);
        size_t off = ((size_t)(n * 256 + q) * 64 + p) * 256 + c0 + seg * 16;
        *(uint4*)&g_Xh[off]     = *(uint4*)&hv[0];
        *(uint4*)&g_Xh[off + 8] = *(uint4*)&hv[8];
        __syncthreads();
    }
}

__global__ void k_pack_w2(const float* __restrict__ Wb, const float* __restrict__ bb,
                          const float* __restrict__ Wc, const float* __restrict__ bc,
                          const float* __restrict__ Wd, const float* __restrict__ bd,
                          const float* __restrict__ alpha) {
    if (alpha[0] == 0.0f) return;
    int i = blockIdx.x * 256 + threadIdx.x;
    int r = i >> 8, c = i & 255;
    float w = 0.0f;
    if (r < 32)       w = Wb[r * 256 + c];
    else if (r < 64)  w = Wc[(r - 32) * 256 + c];
    else if (r < 320) w = Wd[(r - 64) * 256 + c];
    g_Wh[i] = __float2half(w);
    if (i < 320) g_bcat[i] = (i < 32) ? bb[i] : (i < 64) ? bc[i - 32] : bd[i - 64];
}

// ---------------------------------------------------------------------------
// fp16 single-product GEMM via mma.sync.m16n8k16 + ldmatrix.
// Fcat[320][BL] = W(320x256) @ X2^T + b.
// CTA tile M=64 x N=128, K in 4 chunks of 64, double-buffered (55 KB smem,
// 3 CTAs/SM). 8 warps = 2M x 4N, warp tile 32x32.
// ---------------------------------------------------------------------------
constexpr int PAD   = 72;                    // halfs per smem row
constexpr int OFF_B = 64 * PAD;
constexpr int STG   = 192 * PAD;             // 13824 halfs = 27648 B / stage

__global__ void __launch_bounds__(256) k_gemm_mma(const float* __restrict__ a1p,
                                                  const float* __restrict__ a2p, int phase) {
    float a1 = a1p[0];
    if (phase == 0 && a1 != 0.0f) return;
    if (phase == 1 && a1 == 0.0f) return;
    if (a2p[0] == 0.0f) return;

    extern __shared__ __half smb[];
    int t = threadIdx.x, w = t >> 5, lane = t & 31;
    int g = lane >> 2, tg = lane & 3;
    int mt = blockIdx.x;                 // 0..4, fast dim -> B tile L2 reuse
    size_t j0 = (size_t)blockIdx.y * 128;

    uint32_t sbase = smem_u32(smb);
    const __half* Asrc = g_Wh + (size_t)mt * 64 * 256;
    const __half* Bsrc = g_Xh + j0 * 256;

    auto load_chunk = [&](int kc, int s) {
        int k0 = kc * 64;
        uint32_t st = sbase + (uint32_t)s * (STG * 2);
#pragma unroll
        for (int i = 0; i < 2; i++) {          // A: 64 rows x 4 vec16
            int v = t + i * 256, r = v >> 3, sg = v & 7;
            CP16(st + (uint32_t)r * (PAD * 2) + sg * 16, Asrc + (size_t)r * 256 + k0 + sg * 8);
        }
#pragma unroll
        for (int i = 0; i < 4; i++) {          // B: 128 rows x 4 vec16
            int v = t + i * 256, r = v >> 3, sg = v & 7;
            CP16(st + (uint32_t)(OFF_B * 2) + (uint32_t)r * (PAD * 2) + sg * 16,
                 Bsrc + (size_t)r * 256 + k0 + sg * 8);
        }
        CP_COMMIT();
    };

    float d[2][4][4] = {};
    int wm = (w >> 2) * 32;          // warp M offset (0 or 32)
    int wn = (w & 3) * 32;           // warp N offset
    // ldmatrix lane address components
    int a_row = lane & 15,                a_k = (lane >> 4) * 8;
    int b_col = (lane & 7) + (lane >> 4) * 8, b_k = ((lane >> 3) & 1) * 8;

    load_chunk(0, 0);
    load_chunk(1, 1);

#pragma unroll 1
    for (int c = 0; c < 4; c++) {
        if (c < 3) { CP_WAIT(1); } else { CP_WAIT(0); }
        __syncthreads();
        uint32_t st = sbase + (uint32_t)(c & 1) * (STG * 2);
#pragma unroll
        for (int ks = 0; ks < 4; ks++) {
            int k0 = ks * 16;
            uint32_t a[2][4], b[4][2];
#pragma unroll
            for (int mf = 0; mf < 2; mf++) {
                uint32_t addr = st + (uint32_t)((wm + mf * 16 + a_row) * PAD + k0 + a_k) * 2;
                LDSM_X4(a[mf][0], a[mf][1], a[mf][2], a[mf][3], addr);
            }
#pragma unroll
            for (int np = 0; np < 2; np++) {
                uint32_t addr = st + (uint32_t)(OFF_B + (wn + np * 16 + b_col) * PAD + k0 + b_k) * 2;
                LDSM_X4(b[np * 2][0], b[np * 2][1], b[np * 2 + 1][0], b[np * 2 + 1][1], addr);
            }
#pragma unroll
            for (int nf = 0; nf < 4; nf++)
#pragma unroll
                for (int mf = 0; mf < 2; mf++)
                    MMA16816H(d[mf][nf], a[mf], b[nf][0], b[nf][1]);
        }
        __syncthreads();
        if (c + 2 < 4) load_chunk(c + 2, c & 1);
    }

#pragma unroll
    for (int mf = 0; mf < 2; mf++) {
        int row = mt * 64 + wm + mf * 16 + g;
        float b0 = g_bcat[row], b1 = g_bcat[row + 8];
#pragma unroll
        for (int nf = 0; nf < 4; nf++) {
            size_t col = j0 + wn + nf * 8 + 2 * tg;
            *(float2*)&g_Fcat[(size_t)row * BL + col] =
                make_float2(d[mf][nf][0] + b0, d[mf][nf][1] + b0);
            *(float2*)&g_Fcat[(size_t)(row + 8) * BL + col] =
                make_float2(d[mf][nf][2] + b1, d[mf][nf][3] + b1);
        }
    }
}

// ---------------------------------------------------------------------------
// Stage-2 attention (L=64) + EXACT residual + final NCHW store.
// phase 0: residual read straight from NCHW x; phase 1: from Y1t.
// ---------------------------------------------------------------------------
__global__ void __launch_bounds__(256) k_attn2(const float* __restrict__ a1p,
                                               const float* __restrict__ a2p,
                                               const float* __restrict__ x,
                                               float* __restrict__ out, int phase) {
    float a1 = a1p[0];
    if (phase == 0 && a1 != 0.0f) return;
    if (phase == 1 && a1 == 0.0f) return;
    __shared__ float fb_s[32 * 64];
    __shared__ float fc_s[32 * 65];
    __shared__ float P[64 * 65];
    __shared__ float fd_s[64 * 36];
    int b = blockIdx.x, t = threadIdx.x;
    float alpha = a2p[0];
    size_t colbase = (size_t)b * 64;
    int n = b >> 8, q = b & 255, qh = q >> 4, qw = q & 15;

    if (alpha == 0.0f) {
        for (int idx = t; idx < 256 * 64; idx += 256) {
            int c = idx & 255, l = idx >> 8;
            int ph = l >> 3, pw = l & 7;
            size_t o = ((size_t)(n * 256 + c) * 128 + qh * 8 + ph) * 128 + qw * 8 + pw;
            float v = (phase == 0) ? x[o]
                                   : g_Y1t[(size_t)c * BL + (size_t)(n * 64 + l) * 256 + q];
            out[o] = v;
        }
        return;
    }

    const float* __restrict__ FB = g_Fcat;
    const float* __restrict__ FC = g_Fcat + (size_t)32 * BL;
    const float* __restrict__ FD = g_Fcat + (size_t)64 * BL;

    for (int idx = t; idx < 32 * 64; idx += 256) {
        int o = idx >> 6, m = idx & 63;
        fb_s[o * 64 + m] = FB[(size_t)o * BL + colbase + m];
        fc_s[o * 65 + m] = FC[(size_t)o * BL + colbase + m];
    }
    __syncthreads();

    for (int idx = t; idx < 64 * 64; idx += 256) {
        int lt = idx >> 6, m = idx & 63;
        float acc = 0.0f;
#pragma unroll
        for (int o = 0; o < 32; o++) acc += fb_s[o * 64 + lt] * fc_s[o * 65 + m];
        P[lt * 65 + m] = acc;
    }
    __syncthreads();

    int warp = t >> 5, lane = t & 31;
    for (int lt = warp; lt < 64; lt += 8) {
        float v0 = P[lt * 65 + lane], v1 = P[lt * 65 + 32 + lane];
        float mx = fmaxf(v0, v1);
#pragma unroll
        for (int o = 16; o > 0; o >>= 1) mx = fmaxf(mx, __shfl_xor_sync(0xffffffffu, mx, o));
        float e0 = __expf(v0 - mx), e1 = __expf(v1 - mx);
        float s = e0 + e1;
#pragma unroll
        for (int o = 16; o > 0; o >>= 1) s += __shfl_xor_sync(0xffffffffu, s, o);
        float inv = 1.0f / s;
        P[lt * 65 + lane] = e0 * inv;
        P[lt * 65 + 32 + lane] = e1 * inv;
    }
    __syncthreads();

    for (int c0 = 0; c0 < 256; c0 += 32) {
        for (int idx = t; idx < 32 * 64; idx += 256) {
            int m = idx & 63, ci = idx >> 6;
            fd_s[m * 36 + ci] = FD[(size_t)(c0 + ci) * BL + colbase + m];
        }
        __syncthreads();
        for (int idx = t; idx < 512; idx += 256) {
            int lt = idx & 63, ci0 = (idx >> 6) * 4;
            unsigned long long acc0 = 0ull, acc1 = 0ull;
#pragma unroll 4
            for (int m = 0; m < 64; m++) {
                float pv = P[lt * 65 + m];
                unsigned long long pp;
                asm("mov.b64 %0, {%1,%1};" : "=l"(pp) : "r"(__float_as_uint(pv)));
                ulonglong2 f2 = *(const ulonglong2*)&fd_s[m * 36 + ci0];
                asm("fma.rn.f32x2 %0, %1, %2, %3;" : "=l"(acc0) : "l"(f2.x), "l"(pp), "l"(acc0));
                asm("fma.rn.f32x2 %0, %1, %2, %3;" : "=l"(acc1) : "l"(f2.y), "l"(pp), "l"(acc1));
            }
            uint32_t u0, u1, u2, u3;
            asm("mov.b64 {%0,%1}, %2;" : "=r"(u0), "=r"(u1) : "l"(acc0));
            asm("mov.b64 {%0,%1}, %2;" : "=r"(u2), "=r"(u3) : "l"(acc1));
            float a[4] = {__uint_as_float(u0), __uint_as_float(u1),
                          __uint_as_float(u2), __uint_as_float(u3)};
            int ph = lt >> 3, pw = lt & 7;
            size_t o0 = ((size_t)(n * 256 + c0 + ci0) * 128 + qh * 8 + ph) * 128 + qw * 8 + pw;
#pragma unroll
            for (int k = 0; k < 4; k++) {
                float res = (phase == 0)
                    ? x[o0 + (size_t)k * 16384]
                    : g_Y1t[(size_t)(c0 + ci0 + k) * BL + (size_t)(n * 64 + lt) * 256 + q];
                out[o0 + (size_t)k * 16384] = alpha * a[k] + res;
            }
        }
        __syncthreads();
    }
}

// ---------------------------------------------------------------------------
extern "C" void kernel_launch(void* const* d_in, const int* in_sizes, int n_in,
                              void* d_out, int out_size) {
    (void)in_sizes; (void)n_in; (void)out_size;
    const float* x   = (const float*)d_in[0];
    const float* Wb1 = (const float*)d_in[1];
    const float* bb1 = (const float*)d_in[2];
    const float* Wc1 = (const float*)d_in[3];
    const float* bc1 = (const float*)d_in[4];
    const float* Wd1 = (const float*)d_in[5];
    const float* bd1 = (const float*)d_in[6];
    const float* a1  = (const float*)d_in[7];
    const float* Wb2 = (const float*)d_in[8];
    const float* bb2 = (const float*)d_in[9];
    const float* Wc2 = (const float*)d_in[10];
    const float* bc2 = (const float*)d_in[11];
    const float* Wd2 = (const float*)d_in[12];
    const float* bd2 = (const float*)d_in[13];
    const float* a2  = (const float*)d_in[14];
    float* out = (float*)d_out;

    constexpr int GSM = 2 * STG * 2;   // 55296 bytes
    cudaFuncSetAttribute(k_gemm_mma, cudaFuncAttributeMaxDynamicSharedMemorySize, GSM);

    // ---- fast path (alpha1 == 0; all kernels gated on-device) ----
    k_make_X2<<<2048, 256>>>(x, a1, 0);                            // launch 0
    k_pack_w2<<<MR, 256>>>(Wb2, bb2, Wc2, bc2, Wd2, bd2, a2);      // launch 1
    k_pack_w1<<<320, 256>>>(Wb1, bb1, Wc1, bc1, Wd1, bd1, a1);     // launch 2
    k_gemm_mma<<<dim3(5, BL / 128), 256, GSM>>>(a1, a2, 0);        // launch 3 <- profiled
    k_attn2<<<2048, 256>>>(a1, a2, x, out, 0);                     // launch 4

    // ---- rare path (alpha1 != 0; all no-ops otherwise) ----
    k_permute_in<<<8 * 256 * 16, 1024>>>(x, a1);
    k_gemm1<<<dim3(BL / 64, 5), 256>>>(a1);
    k_attn1<<<512 * 8, 256>>>(a1);
    k_make_X2<<<2048, 256>>>(x, a1, 1);
    k_gemm_mma<<<dim3(5, BL / 128), 256, GSM>>>(a1, a2, 1);
    k_attn2<<<2048, 256>>>(a1, a2, x, out, 1);
}